// round 14
// baseline (speedup 1.0000x reference)
#include <cuda_runtime.h>
#include <math.h>

#define NB 8
#define NC 19
#define HW (512 * 512)
#define HW2 (HW / 2)
#define SMOOTH 1e-08f
#define GRID_X 37
#define NBLOCKS (GRID_X * NB)
#define NTHREADS 256

__device__ float g_acc[2 * NB * NC];   // [0..152)=tp, [152..304)=den
__device__ unsigned int g_done = 0;

// ---- packed f32x2 helpers (sm_103a; ptxas only emits these from PTX) ----
__device__ __forceinline__ void mul2(float2& d, const float2 a, const float2 b) {
    asm("{\n\t.reg .b64 ra, rb, rd;\n\t"
        "mov.b64 ra, {%2,%3};\n\tmov.b64 rb, {%4,%5};\n\t"
        "mul.rn.f32x2 rd, ra, rb;\n\t"
        "mov.b64 {%0,%1}, rd;\n\t}"
        : "=f"(d.x), "=f"(d.y)
        : "f"(a.x), "f"(a.y), "f"(b.x), "f"(b.y));
}
__device__ __forceinline__ void add2(float2& d, const float2 a) {
    asm("{\n\t.reg .b64 ra, rd;\n\t"
        "mov.b64 ra, {%2,%3};\n\tmov.b64 rd, {%0,%1};\n\t"
        "add.rn.f32x2 rd, rd, ra;\n\t"
        "mov.b64 {%0,%1}, rd;\n\t}"
        : "+f"(d.x), "+f"(d.y)
        : "f"(a.x), "f"(a.y));
}
__device__ __forceinline__ void fma2(float2& d, const float2 a, const float2 b) {
    asm("{\n\t.reg .b64 ra, rb, rd;\n\t"
        "mov.b64 ra, {%2,%3};\n\tmov.b64 rb, {%4,%5};\n\tmov.b64 rd, {%0,%1};\n\t"
        "fma.rn.f32x2 rd, ra, rb, rd;\n\t"
        "mov.b64 {%0,%1}, rd;\n\t}"
        : "+f"(d.x), "+f"(d.y)
        : "f"(a.x), "f"(a.y), "f"(b.x), "f"(b.y));
}
__device__ __forceinline__ float ex2f(float x) {
    asm("ex2.approx.f32 %0, %0;" : "+f"(x));
    return x;
}
__device__ __forceinline__ void pf_l2(const void* p) {
    asm volatile("prefetch.global.L2 [%0];" :: "l"(p));
}

__global__ __launch_bounds__(NTHREADS, 2) void tversky_fused_kernel(
    const float* __restrict__ pred, const int* __restrict__ target,
    float* __restrict__ out) {
    const int b = blockIdx.y;
    const float2* __restrict__ p2 =
        (const float2*)(pred + (size_t)b * NC * HW);
    const int2* __restrict__ t2 = (const int2*)(target + (size_t)b * HW);
    const int tid = threadIdx.x;
    const int lane = tid & 31;

    __shared__ float s_acc[2 * NC];   // tp, den
    __shared__ int s_is_last;
    if (tid < 2 * NC) s_acc[tid] = 0.0f;
    __syncthreads();

    float rtp[NC];
    float2 rden[NC];
#pragma unroll
    for (int c = 0; c < NC; c++) { rtp[c] = 0.0f; rden[c] = make_float2(0.0f, 0.0f); }

    // lane -> (class, 128B-half) mapping for deduplicated prefetch:
    // a warp touches 19 classes x 2 lines (256B) + 2 target lines = 40 lines.
    const int pfc0 = lane >> 1;            // classes 0..15
    const int pfc1 = 16 + (pfc0 & 3);      // classes 16..18 (lane 0..5)
    const int pfh = (lane & 1) << 7;       // 0 or 128 byte offset

    const float2 LOG2E2 = make_float2(1.4426950408889634f, 1.4426950408889634f);
    const int stride = GRID_X * NTHREADS;
    for (int idx = blockIdx.x * NTHREADS + tid; idx < HW2; idx += stride) {
        float2 e[NC];
#pragma unroll
        for (int c = 0; c < NC; c++) e[c] = __ldcs(&p2[(size_t)c * HW2 + idx]);
        const int2 tg = __ldcs(&t2[idx]);

        // deduplicated prefetch stream, 2 grid-strides ahead: keeps DRAM
        // row-open requests flowing while warps sit in the compute phase
        const int pw = (idx - lane) + 2 * stride;   // warp-aligned base
        if (pw < HW2) {
            pf_l2((const char*)(p2 + (size_t)pfc0 * HW2 + pw) + pfh);
            if (lane < 6)
                pf_l2((const char*)(p2 + (size_t)pfc1 * HW2 + pw) + pfh);
            if (lane == 6 || lane == 7)
                pf_l2((const char*)(t2 + pw) + ((lane - 6) << 7));
        }

        float2 sum2 = make_float2(0.0f, 0.0f);
#pragma unroll
        for (int c = 0; c < NC; c++) {
            mul2(e[c], e[c], LOG2E2);        // x * log2(e)   (packed)
            e[c].x = ex2f(e[c].x);           // 2^x = exp
            e[c].y = ex2f(e[c].y);
            add2(sum2, e[c]);                // packed accumulate
        }
        const float rx = __fdividef(1.0f, sum2.x);
        const float ry = __fdividef(1.0f, sum2.y);
        const float2 r2 = make_float2(rx, ry);

#pragma unroll
        for (int c = 0; c < NC; c++) {
            fma2(rden[c], e[c], r2);         // rden += e * r  (packed)
            if (tg.x == c) { rtp[c] = fmaf(e[c].x, rx, rtp[c]); rden[c].x += 1.0f; }
            if (tg.y == c) { rtp[c] = fmaf(e[c].y, ry, rtp[c]); rden[c].y += 1.0f; }
        }
    }

    // fold packed halves, warp-reduce the 38 accumulators
    float rdn[NC];
#pragma unroll
    for (int c = 0; c < NC; c++) rdn[c] = rden[c].x + rden[c].y;
#pragma unroll
    for (int c = 0; c < NC; c++) {
#pragma unroll
        for (int off = 16; off > 0; off >>= 1) {
            rtp[c] += __shfl_down_sync(0xFFFFFFFFu, rtp[c], off);
            rdn[c] += __shfl_down_sync(0xFFFFFFFFu, rdn[c], off);
        }
    }
    if ((tid & 31) == 0) {
#pragma unroll
        for (int c = 0; c < NC; c++) {
            atomicAdd(&s_acc[c], rtp[c]);
            atomicAdd(&s_acc[NC + c], rdn[c]);
        }
    }
    __syncthreads();

    // block -> global (38 atomics from first 38 threads)
    if (tid < 2 * NC) {
        const int sec = tid / NC;
        const int c = tid - sec * NC;
        atomicAdd(&g_acc[sec * NB * NC + b * NC + c], s_acc[tid]);
    }

    // last-block-done epilogue
    __threadfence();
    if (tid == 0) {
        unsigned int n = atomicAdd(&g_done, 1u);
        s_is_last = (n == NBLOCKS - 1);
    }
    __syncthreads();
    if (!s_is_last) return;

    __shared__ float s_red[NTHREADS];
    float v = 0.0f;
    if (tid < NB * NC) {
        const float tp = __ldcg(&g_acc[tid]);
        const float dn = __ldcg(&g_acc[NB * NC + tid]);
        v = 1.0f - (tp + SMOOTH) / (0.5f * dn + SMOOTH);  // alpha=beta=0.5
    }
    s_red[tid] = v;
    __syncthreads();
#pragma unroll
    for (int off = NTHREADS / 2; off > 0; off >>= 1) {
        if (tid < off) s_red[tid] += s_red[tid + off];
        __syncthreads();
    }
    if (tid == 0) {
        out[0] = s_red[0] / (float)(NB * NC);
        g_done = 0u;
    }
    for (int i = tid; i < 2 * NB * NC; i += NTHREADS) g_acc[i] = 0.0f;
}

extern "C" void kernel_launch(void* const* d_in, const int* in_sizes, int n_in,
                              void* d_out, int out_size) {
    const float* pred = (const float*)d_in[0];
    const int* target = (const int*)d_in[1];
    float* out = (float*)d_out;

    dim3 grid(GRID_X, NB);
    tversky_fused_kernel<<<grid, NTHREADS>>>(pred, target, out);
}